// round 10
// baseline (speedup 1.0000x reference)
#include <cuda_runtime.h>

#define NB 8
#define NV 256
#define ND 64
#define NH 128
#define NI 32
#define NT 50
#define ROWS 16
#define XS 20                 // smem activation stride
#define NTHR 512
#define GRID 128              // 16 blocks per batch element = 1 cluster
#define CLUSTER 16

// ---- shared memory layout (floats) ----
#define WORK0 0               // 4096  (adj tile / xA / gru region0)
#define WORK1 4096            // 4096  (partials / xB / rT,zT)
#define W_IN  8192            // 8192  (64x128)
#define W_H0  16384           // 16384 (128x128)
#define W_H1  32768           // 16384 (128x128)
#define W_OUT 49152           // 8192  (128x64)
#define SM_FLOATS 57344       // 224 KB
// GRU overlay (reuses W_H0/W_H1 space; reloaded after GRU)
#define G_WR  16384           // 96x64 = 6144
#define G_WZ  (16384 + 6144)
#define G_WG  (16384 + 12288)
#define G_WO  (16384 + 18432) // 64x32 = 2048

__device__ __forceinline__ float fast_tanh(float x) {
    float e = __expf(-2.0f * fabsf(x));
    float t = __fdividef(1.0f - e, 1.0f + e);
    return copysignf(t, x);
}
__device__ __forceinline__ float fast_sig(float x) {
    return __fdividef(1.0f, 1.0f + __expf(-x));
}

__device__ __forceinline__ void cluster_barrier() {
    __syncthreads();
    __threadfence();
    asm volatile("barrier.cluster.arrive.aligned;" ::: "memory");
    asm volatile("barrier.cluster.wait.aligned;" ::: "memory");
}

__device__ __forceinline__ void smcopy(float* dst, const float* src, int nfloats, int t) {
    float4* d4 = (float4*)dst;
    const float4* s4 = (const float4*)src;
    int n4 = nfloats >> 2;
    for (int i = t; i < n4; i += NTHR) d4[i] = s4[i];
}

// hidden layer, Kout=128: 16 rows x 128 cols, 512 threads, tile = 4 rows x 1 col.
// xin/xout in [k][row] layout (stride XS); W (smem) row-major [k][128].
template <int KIN>
__device__ __forceinline__ void layer128(int t, const float* W,
                                         const float* __restrict__ bias,
                                         const float* xin, float* xout) {
    const int c = t & 127;
    const int r4 = (t >> 7) * 4;
    float b = __ldg(bias + c);
    float a0 = 0.f, a1 = 0.f, a2 = 0.f, a3 = 0.f;
    const float* xp = xin + r4;
    const float* wp = W + c;
#pragma unroll 8
    for (int k = 0; k < KIN; k++) {
        float4 xv = *(const float4*)xp;
        float wv = *wp;
        xp += XS;
        wp += NH;
        a0 += xv.x * wv; a1 += xv.y * wv; a2 += xv.z * wv; a3 += xv.w * wv;
    }
    xout[c * XS + r4 + 0] = fast_tanh(a0 + b);
    xout[c * XS + r4 + 1] = fast_tanh(a1 + b);
    xout[c * XS + r4 + 2] = fast_tanh(a2 + b);
    xout[c * XS + r4 + 3] = fast_tanh(a3 + b);
}

// stage adj tile (16x256) into WORK0, then agg = adj @ h -> WORK0 as [d][r] (stride XS).
// 512 threads: d4(16) x rg(4 groups of 4 rows) x ws(8 chunks of 32 w).
__device__ __forceinline__ void stage_agg(float* sm, int t, const float* __restrict__ adjb,
                                          const float* __restrict__ hb, int bcast) {
#pragma unroll
    for (int i = 0; i < 2; i++) {
        int idx = t + i * NTHR;  // float4 index, 0..1023
        *(float4*)(sm + idx * 4) = *(const float4*)(adjb + idx * 4);
    }
    __syncthreads();
    const int d4 = (t & 15) * 4;
    const int rg = ((t >> 4) & 3) * 4;
    const int ws = t >> 6;               // 0..7
    float4 acc[4];
    acc[0] = acc[1] = acc[2] = acc[3] = make_float4(0.f, 0.f, 0.f, 0.f);
    {
        const int wstride = bcast ? 0 : ND;
        const float* hbase = bcast ? (hb + d4) : (hb + (long long)(ws * 32) * ND + d4);
#pragma unroll 4
        for (int w = 0; w < 32; w++) {
            float4 h4 = *(const float4*)(hbase + (long long)w * wstride);
            int wa = ws * 32 + w;
#pragma unroll
            for (int rr = 0; rr < 4; rr++) {
                float a = sm[(rg + rr) * NV + wa];
                acc[rr].x += a * h4.x; acc[rr].y += a * h4.y;
                acc[rr].z += a * h4.z; acc[rr].w += a * h4.w;
            }
        }
    }
    float* pb = sm + WORK1;
    if (ws < 4) {
#pragma unroll
        for (int rr = 0; rr < 4; rr++)
            *(float4*)(pb + ws * 1024 + (rg + rr) * ND + d4) = acc[rr];
    }
    __syncthreads();
    if (ws >= 4) {
#pragma unroll
        for (int rr = 0; rr < 4; rr++) {
            float4* p = (float4*)(pb + (ws - 4) * 1024 + (rg + rr) * ND + d4);
            float4 v = *p;
            v.x += acc[rr].x; v.y += acc[rr].y; v.z += acc[rr].z; v.w += acc[rr].w;
            *p = v;
        }
    }
    __syncthreads();
#pragma unroll
    for (int i = 0; i < 2; i++) {
        int idx = t + i * NTHR;  // 0..1023
        int r = idx >> 6, d = idx & 63;
        float s = pb[d + r * ND] + pb[1024 + d + r * ND] +
                  pb[2048 + d + r * ND] + pb[3072 + d + r * ND];
        sm[WORK0 + d * XS + r] = s;
    }
    __syncthreads();
}

// one Euler substep: out = h + DT * tanh(MLP(adj @ h))
__device__ void euler_step(float* sm, int t, const float* __restrict__ adjb,
                           const float* __restrict__ hb, int bcast, int v0,
                           const float* __restrict__ bin,
                           const float* __restrict__ bh0,
                           const float* __restrict__ bh1,
                           const float* __restrict__ bout,
                           float* __restrict__ out1, float* __restrict__ out2) {
    stage_agg(sm, t, adjb, hb, bcast);
    float* xA = sm + WORK0;
    float* xB = sm + WORK1;
    layer128<ND>(t, sm + W_IN, bin, xA, xB);
    __syncthreads();
    layer128<NH>(t, sm + W_H0, bh0, xB, xA);
    __syncthreads();
    layer128<NH>(t, sm + W_H1, bh1, xA, xB);
    __syncthreads();
    // final layer 128 -> 64, tile = 2 rows x 1 col
    {
        const int c = t & 63;
        const int r2 = (t >> 6) * 2;
        float b = __ldg(bout + c);
        float a0 = 0.f, a1 = 0.f;
        const float* xp = xB + r2;
        const float* wp = sm + W_OUT + c;
#pragma unroll 8
        for (int k = 0; k < NH; k++) {
            float2 xv = *(const float2*)xp;
            float wv = *wp;
            xp += XS;
            wp += ND;
            a0 += xv.x * wv; a1 += xv.y * wv;
        }
#pragma unroll
        for (int rr = 0; rr < 2; rr++) {
            int r = r2 + rr;
            float hp = bcast ? hb[c] : hb[(v0 + r) * ND + c];
            float d = (rr == 0) ? a0 : a1;
            float o = hp + 0.25f * fast_tanh(d + b);
            out1[(v0 + r) * ND + c] = o;
            if (out2) out2[(v0 + r) * ND + c] = o;
        }
    }
}

// GRU correction; weights from smem overlay. Also writes x_pred row (xp != null).
__device__ void gru_step(float* sm, int t, const float* __restrict__ adjb,
                         const float* __restrict__ hb, int v0,
                         const float* __restrict__ vrow, const float* __restrict__ mrowg,
                         const float* __restrict__ br, const float* __restrict__ bz,
                         const float* __restrict__ bg, const float* __restrict__ bo,
                         float* __restrict__ post, float* __restrict__ xp) {
    float* aggT = sm + WORK0;            // 64*XS
    float* h1T = sm + WORK0 + 64 * XS;   // 64*XS
    float* xT = sm + WORK0 + 128 * XS;   // 32*XS
    float* mrow = sm + WORK0 + 160 * XS; // 16
    float* rT = sm + WORK1;
    float* zT = sm + WORK1 + 64 * XS;

    // stage adj + agg (same pattern as euler, plus h1T/xT/mrow staging)
#pragma unroll
    for (int i = 0; i < 2; i++) {
        int idx = t + i * NTHR;
        *(float4*)(sm + idx * 4) = *(const float4*)(adjb + idx * 4);
    }
    __syncthreads();
    {
        const int d4 = (t & 15) * 4;
        const int rg = ((t >> 4) & 3) * 4;
        const int ws = t >> 6;
        float4 acc[4];
        acc[0] = acc[1] = acc[2] = acc[3] = make_float4(0.f, 0.f, 0.f, 0.f);
        const float* hbase = hb + (long long)(ws * 32) * ND + d4;
#pragma unroll 4
        for (int w = 0; w < 32; w++) {
            float4 h4 = *(const float4*)(hbase + (long long)w * ND);
            int wa = ws * 32 + w;
#pragma unroll
            for (int rr = 0; rr < 4; rr++) {
                float a = sm[(rg + rr) * NV + wa];
                acc[rr].x += a * h4.x; acc[rr].y += a * h4.y;
                acc[rr].z += a * h4.z; acc[rr].w += a * h4.w;
            }
        }
        float* pb = sm + WORK1;
        if (ws < 4) {
#pragma unroll
            for (int rr = 0; rr < 4; rr++)
                *(float4*)(pb + ws * 1024 + (rg + rr) * ND + d4) = acc[rr];
        }
        __syncthreads();
        if (ws >= 4) {
#pragma unroll
            for (int rr = 0; rr < 4; rr++) {
                float4* p = (float4*)(pb + (ws - 4) * 1024 + (rg + rr) * ND + d4);
                float4 v = *p;
                v.x += acc[rr].x; v.y += acc[rr].y; v.z += acc[rr].z; v.w += acc[rr].w;
                *p = v;
            }
        }
        __syncthreads();
    }
    {
        const float* pb = sm + WORK1;
#pragma unroll
        for (int i = 0; i < 2; i++) {
            int idx = t + i * NTHR;
            int r = idx >> 6, d = idx & 63;
            float s = pb[d + r * ND] + pb[1024 + d + r * ND] +
                      pb[2048 + d + r * ND] + pb[3072 + d + r * ND];
            aggT[d * XS + r] = s;
            h1T[d * XS + r] = hb[(v0 + r) * ND + d];
        }
    }
    {
        int r = t >> 5, c = t & 31;  // 512 threads = 16 rows x 32 cols
        xT[c * XS + r] = vrow[(v0 + r) * NI + c] * mrowg[(v0 + r) * NI + c];
        if (t < ROWS) {
            float s = 0.f;
            for (int cc = 0; cc < NI; cc++) s += fabsf(mrowg[(v0 + t) * NI + cc]);
            mrow[t] = (s > 1e-4f) ? 1.0f : 0.0f;
        }
    }
    __syncthreads();

    const int c = t & 63;
    const int r2 = (t >> 6) * 2;
    // r and z gates (Kin = 96 = [x(32), agg(64)]), tile = 2 rows x 1 col
    {
        float brc = __ldg(br + c), bzc = __ldg(bz + c);
        float ar0 = 0.f, ar1 = 0.f, az0 = 0.f, az1 = 0.f;
        const float* wr = sm + G_WR + c;
        const float* wz = sm + G_WZ + c;
        const float* xq = xT + r2;
#pragma unroll 8
        for (int k = 0; k < NI; k++) {
            float2 xv = *(const float2*)xq;
            float wrv = *wr, wzv = *wz;
            xq += XS; wr += ND; wz += ND;
            ar0 += xv.x * wrv; ar1 += xv.y * wrv;
            az0 += xv.x * wzv; az1 += xv.y * wzv;
        }
        const float* xa = aggT + r2;
#pragma unroll 8
        for (int k = 0; k < ND; k++) {
            float2 xv = *(const float2*)xa;
            float wrv = *wr, wzv = *wz;
            xa += XS; wr += ND; wz += ND;
            ar0 += xv.x * wrv; ar1 += xv.y * wrv;
            az0 += xv.x * wzv; az1 += xv.y * wzv;
        }
        rT[c * XS + r2 + 0] = fast_sig(ar0 + brc);
        rT[c * XS + r2 + 1] = fast_sig(ar1 + brc);
        zT[c * XS + r2 + 0] = fast_sig(az0 + bzc);
        zT[c * XS + r2 + 1] = fast_sig(az1 + bzc);
    }
    __syncthreads();
    // rT <- r * agg (elementwise)
#pragma unroll
    for (int i = 0; i < 2; i++) {
        int idx = t + i * NTHR;
        int r = idx >> 6, d = idx & 63;
        rT[d * XS + r] *= aggT[d * XS + r];
    }
    __syncthreads();
    // g gate + combine + store post
    {
        float bgc = __ldg(bg + c);
        float ag0 = 0.f, ag1 = 0.f;
        const float* wg = sm + G_WG + c;
        const float* xq = xT + r2;
#pragma unroll 8
        for (int k = 0; k < NI; k++) {
            float2 xv = *(const float2*)xq;
            float wgv = *wg;
            xq += XS; wg += ND;
            ag0 += xv.x * wgv; ag1 += xv.y * wgv;
        }
        const float* xr = rT + r2;
#pragma unroll 8
        for (int k = 0; k < ND; k++) {
            float2 xv = *(const float2*)xr;
            float wgv = *wg;
            xr += XS; wg += ND;
            ag0 += xv.x * wgv; ag1 += xv.y * wgv;
        }
#pragma unroll
        for (int rr = 0; rr < 2; rr++) {
            int r = r2 + rr;
            float m = mrow[r];
            float g = fast_tanh(((rr == 0) ? ag0 : ag1) + bgc);
            float z = zT[c * XS + r];
            float hv = h1T[c * XS + r];
            float n = (1.f - z) * hv + z * g;
            post[(v0 + r) * ND + c] = hv + m * (n - hv);
        }
    }
    // x_pred row from h1 (pre state): 512 threads = 16 rows x 32 cols
    if (xp) {
        const int cx = t & 31;
        const int r = t >> 5;
        float a0 = 0.f;
        const float* wo = sm + G_WO + cx;
        const float* hq = h1T + r;
#pragma unroll 8
        for (int k = 0; k < ND; k++) {
            a0 += (*hq) * (*wo);
            hq += XS; wo += NI;
        }
        xp[(v0 + r) * NI + cx] = a0 + __ldg(bo + cx);
    }
}

__global__ void init_kernel(float* __restrict__ trj) {
    int i = threadIdx.x;
    if (i < 197) trj[i] = 0.25f * (float)i;
}

__global__ void __launch_bounds__(NTHR, 1) __cluster_dims__(CLUSTER, 1, 1)
node_persist(
    const float* __restrict__ values, const float* __restrict__ masks,
    const float* __restrict__ adj, const float* __restrict__ h0,
    const float* __restrict__ Wo_g, const float* __restrict__ bo,
    const float* __restrict__ Win_g, const float* __restrict__ bin,
    const float* __restrict__ Wh_g, const float* __restrict__ bh,
    const float* __restrict__ Wode_g, const float* __restrict__ bode,
    const float* __restrict__ Wr_g, const float* __restrict__ br,
    const float* __restrict__ Wz_g, const float* __restrict__ bz,
    const float* __restrict__ Wg_g, const float* __restrict__ bg,
    float* __restrict__ XP, float* __restrict__ PRE,
    float* __restrict__ PREN, float* __restrict__ POST) {
    extern __shared__ __align__(16) float sm[];
    const int t = threadIdx.x;
    const int b = blockIdx.x >> 4;
    const int v0 = (blockIdx.x & 15) * ROWS;
    const float* adjb = adj + ((long long)b * NV + v0) * NV;
    const long long SL = (long long)NV * ND;
    float* PREb = PRE + (long long)b * 197 * SL;
    float* PRENb = PREN + (long long)b * NT * SL;
    float* POSTb = POST + (long long)b * NT * SL;
    float* XPb = XP + (long long)b * 49 * NV * NI;
    const float* valb = values + (long long)b * NT * NV * NI;
    const float* mskb = masks + (long long)b * NT * NV * NI;

    // weights resident in smem for the whole kernel
    smcopy(sm + W_IN, Win_g, 8192, t);
    smcopy(sm + W_H0, Wh_g, 16384, t);
    smcopy(sm + W_H1, Wh_g + 16384, 16384, t);
    smcopy(sm + W_OUT, Wode_g, 8192, t);
    __syncthreads();

    // t=0: single Euler from broadcast h0
    euler_step(sm, t, adjb, h0, 1, v0, bin, bh, bh + NH, bode, PREb, PRENb);
    cluster_barrier();

    for (int tt = 0; tt < NT; tt++) {
        // overlay GRU weights into W_H0/W_H1 space
        smcopy(sm + G_WR, Wr_g, 6144, t);
        smcopy(sm + G_WZ, Wz_g, 6144, t);
        smcopy(sm + G_WG, Wg_g, 6144, t);
        smcopy(sm + G_WO, Wo_g, 2048, t);
        __syncthreads();
        gru_step(sm, t, adjb, PRENb + (long long)tt * SL, v0,
                 valb + (long long)tt * NV * NI, mskb + (long long)tt * NV * NI,
                 br, bz, bg, bo, POSTb + (long long)tt * SL,
                 tt ? (XPb + (long long)(tt - 1) * NV * NI) : nullptr);
        cluster_barrier();
        if (tt < NT - 1) {
            // restore Wh0/Wh1
            smcopy(sm + W_H0, Wh_g, 16384, t);
            smcopy(sm + W_H1, Wh_g + 16384, 16384, t);
            __syncthreads();
            const float* hin = POSTb + (long long)tt * SL;
#pragma unroll 1
            for (int k = 0; k < 4; k++) {
                float* o1 = PREb + (long long)(1 + 4 * tt + k) * SL;
                float* o2 = (k == 3) ? (PRENb + (long long)(tt + 1) * SL) : nullptr;
                euler_step(sm, t, adjb, hin, 0, v0, bin, bh, bh + NH, bode, o1, o2);
                cluster_barrier();
                hin = o1;
            }
        }
    }
}

extern "C" void kernel_launch(void* const* d_in, const int* in_sizes, int n_in,
                              void* d_out, int out_size) {
    const float* values = (const float*)d_in[0];
    const float* masks  = (const float*)d_in[1];
    const float* adj    = (const float*)d_in[2];
    const float* h0     = (const float*)d_in[3];
    const float* W_out  = (const float*)d_in[4];
    const float* b_out  = (const float*)d_in[5];
    const float* Win    = (const float*)d_in[6];
    const float* bin    = (const float*)d_in[7];
    const float* Wh     = (const float*)d_in[8];
    const float* bh     = (const float*)d_in[9];
    const float* Wode   = (const float*)d_in[10];
    const float* bode   = (const float*)d_in[11];
    const float* Wr     = (const float*)d_in[12];
    const float* br     = (const float*)d_in[13];
    const float* Wz     = (const float*)d_in[14];
    const float* bz     = (const float*)d_in[15];
    const float* Wg     = (const float*)d_in[16];
    const float* bg     = (const float*)d_in[17];

    float* out = (float*)d_out;
    float* XP   = out;                                        // (8,49,256,32)
    float* PRE  = XP + (long long)NB * 49 * NV * NI;          // (8,197,256,64)
    float* PREN = PRE + (long long)NB * 197 * NV * ND;        // (8,50,256,64)
    float* POST = PREN + (long long)NB * NT * NV * ND;        // (8,50,256,64)
    float* TRJ  = POST + (long long)NB * NT * NV * ND;        // (197,)

    const size_t smbytes = SM_FLOATS * sizeof(float);         // 229376
    static int configured = 0;
    if (!configured) {
        cudaFuncSetAttribute(node_persist,
                             cudaFuncAttributeNonPortableClusterSizeAllowed, 1);
        cudaFuncSetAttribute(node_persist,
                             cudaFuncAttributeMaxDynamicSharedMemorySize, (int)smbytes);
        configured = 1;
    }

    init_kernel<<<1, 256>>>(TRJ);
    node_persist<<<GRID, NTHR, smbytes>>>(values, masks, adj, h0, W_out, b_out,
                                          Win, bin, Wh, bh, Wode, bode,
                                          Wr, br, Wz, bz, Wg, bg,
                                          XP, PRE, PREN, POST);
}

// round 11
// speedup vs baseline: 1.2001x; 1.2001x over previous
#include <cuda_runtime.h>

#define NB 8
#define NV 256
#define ND 64
#define NH 128
#define NI 32
#define NT 50
#define ROWS 16
#define XS 20                 // smem activation stride
#define NTHR 256
#define GRID 128              // 16 blocks per batch element = 1 cluster
#define CLUSTER 16

// ---- shared memory layout (floats) ----
#define WORK0 0               // 4096  (adj tile / xA / gru region0)
#define WORK1 4096            // 4096  (h chunk double-buffer / partials / xB / rT,zT)
#define W_IN  8192            // 8192  (64x128)
#define W_H0  16384           // 16384 (128x128)
#define W_H1  32768           // 16384 (128x128)
#define W_OUT 49152           // 8192  (128x64)
#define SM_FLOATS 57344       // 224 KB
// GRU overlay (reuses W_H0/W_H1 space; reloaded after GRU)
#define G_WR  16384           // 96x64 = 6144
#define G_WZ  (16384 + 6144)
#define G_WG  (16384 + 12288)
#define G_WO  (16384 + 18432) // 64x32 = 2048

__device__ __forceinline__ float fast_tanh(float x) {
    float e = __expf(-2.0f * fabsf(x));
    float t = __fdividef(1.0f - e, 1.0f + e);
    return copysignf(t, x);
}
__device__ __forceinline__ float fast_sig(float x) {
    return __fdividef(1.0f, 1.0f + __expf(-x));
}

__device__ __forceinline__ void cluster_barrier() {
    __syncthreads();
    __threadfence();
    asm volatile("barrier.cluster.arrive.aligned;" ::: "memory");
    asm volatile("barrier.cluster.wait.aligned;" ::: "memory");
}

__device__ __forceinline__ void smcopy(float* dst, const float* src, int nfloats, int t) {
    float4* d4 = (float4*)dst;
    const float4* s4 = (const float4*)src;
    int n4 = nfloats >> 2;
    for (int i = t; i < n4; i += NTHR) d4[i] = s4[i];
}

// hidden layer, Kout=128: 16 rows x 128 cols, 256 threads, tile 4 rows x 2 cols.
// W in shared memory. xin/xout in [k][row] layout, stride XS.
template <int KIN>
__device__ __forceinline__ void layer128(int t, const float* W,
                                         const float* __restrict__ bias,
                                         const float* xin, float* xout) {
    const int c2 = (t & 63) * 2;
    const int r4 = (t >> 6) * 4;
    float b0 = __ldg(bias + c2), b1 = __ldg(bias + c2 + 1);
    float a00 = 0.f, a01 = 0.f, a10 = 0.f, a11 = 0.f;
    float a20 = 0.f, a21 = 0.f, a30 = 0.f, a31 = 0.f;
    const float* xp = xin + r4;
    const float* wp = W + c2;
#pragma unroll 4
    for (int k = 0; k < KIN; k++) {
        float4 xv = *(const float4*)xp;
        float2 wv = *(const float2*)wp;
        xp += XS;
        wp += NH;
        a00 += xv.x * wv.x; a01 += xv.x * wv.y;
        a10 += xv.y * wv.x; a11 += xv.y * wv.y;
        a20 += xv.z * wv.x; a21 += xv.z * wv.y;
        a30 += xv.w * wv.x; a31 += xv.w * wv.y;
    }
    xout[c2 * XS + r4 + 0] = fast_tanh(a00 + b0);
    xout[c2 * XS + r4 + 1] = fast_tanh(a10 + b0);
    xout[c2 * XS + r4 + 2] = fast_tanh(a20 + b0);
    xout[c2 * XS + r4 + 3] = fast_tanh(a30 + b0);
    xout[(c2 + 1) * XS + r4 + 0] = fast_tanh(a01 + b1);
    xout[(c2 + 1) * XS + r4 + 1] = fast_tanh(a11 + b1);
    xout[(c2 + 1) * XS + r4 + 2] = fast_tanh(a21 + b1);
    xout[(c2 + 1) * XS + r4 + 3] = fast_tanh(a31 + b1);
}

// agg = adj @ h -> WORK0 as [d][r] (stride XS).
// h is streamed through smem in 8 chunks of 32 rows (8KB), double-buffered in
// WORK1; after the last chunk, WORK1 is reused for the wq-partial buffer.
// Thread map: d4 = (t&15)*4, rg = ((t>>4)&3)*4, wq = t>>6 (quarter of each chunk).
__device__ __forceinline__ void stage_agg(float* sm, int t, const float* __restrict__ adjb,
                                          const float* __restrict__ hb, int bcast) {
    const int d4 = (t & 15) * 4;
    const int rg = ((t >> 4) & 3) * 4;
    const int wq = t >> 6;  // 0..3
    float4 acc[4];
    acc[0] = acc[1] = acc[2] = acc[3] = make_float4(0.f, 0.f, 0.f, 0.f);

    if (bcast) {
        float4 h4 = *(const float4*)(hb + d4);   // h0 broadcast (64 floats)
        // stage adj tile
#pragma unroll
        for (int i = 0; i < 4; i++) {
            int idx = t + i * NTHR;
            *(float4*)(sm + idx * 4) = *(const float4*)(adjb + idx * 4);
        }
        __syncthreads();
#pragma unroll 4
        for (int w = 0; w < 64; w++) {
            int wa = wq * 64 + w;
#pragma unroll
            for (int rr = 0; rr < 4; rr++) {
                float a = sm[(rg + rr) * NV + wa];
                acc[rr].x += a * h4.x; acc[rr].y += a * h4.y;
                acc[rr].z += a * h4.z; acc[rr].w += a * h4.w;
            }
        }
        __syncthreads();
    } else {
        float* hbuf = sm + WORK1;  // 2 x 2048 floats (32 rows x 64 each)
        // prefetch chunk 0 into registers
        float4 p0 = *(const float4*)(hb + t * 8);
        float4 p1 = *(const float4*)(hb + t * 8 + 4);
        // stage adj tile
#pragma unroll
        for (int i = 0; i < 4; i++) {
            int idx = t + i * NTHR;
            *(float4*)(sm + idx * 4) = *(const float4*)(adjb + idx * 4);
        }
        *(float4*)(hbuf + t * 8) = p0;
        *(float4*)(hbuf + t * 8 + 4) = p1;
#pragma unroll 2
        for (int c = 0; c < 8; c++) {
            float4 q0, q1;
            if (c < 7) {
                const float* src = hb + (c + 1) * 2048 + t * 8;
                q0 = *(const float4*)src;
                q1 = *(const float4*)(src + 4);
            }
            __syncthreads();  // chunk c staged; previous compute done
            const float* hc = hbuf + (c & 1) * 2048;
#pragma unroll
            for (int w = 0; w < 8; w++) {
                int wl = wq * 8 + w;            // row within chunk
                float4 h4 = *(const float4*)(hc + wl * 64 + d4);
                int wa = c * 32 + wl;           // adj column
#pragma unroll
                for (int rr = 0; rr < 4; rr++) {
                    float a = sm[(rg + rr) * NV + wa];
                    acc[rr].x += a * h4.x; acc[rr].y += a * h4.y;
                    acc[rr].z += a * h4.z; acc[rr].w += a * h4.w;
                }
            }
            if (c < 7) {
                float* dst = hbuf + ((c + 1) & 1) * 2048 + t * 8;
                *(float4*)dst = q0;
                *(float4*)(dst + 4) = q1;
            }
        }
        __syncthreads();  // all chunk compute done; hbuf now dead
    }

    // wq-partials into WORK1 (h buffer dead)
    float* pb = sm + WORK1;
#pragma unroll
    for (int rr = 0; rr < 4; rr++)
        *(float4*)(pb + wq * 1024 + (rg + rr) * ND + d4) = acc[rr];
    __syncthreads();
    // reduce 4 partials -> xA [d][r] in WORK0 (adj dead)
#pragma unroll
    for (int i = 0; i < 4; i++) {
        int idx = t + i * NTHR;  // 0..1023
        int r = idx >> 6, d = idx & 63;
        float s = pb[d + r * ND] + pb[1024 + d + r * ND] +
                  pb[2048 + d + r * ND] + pb[3072 + d + r * ND];
        sm[WORK0 + d * XS + r] = s;
    }
    __syncthreads();
}

// one Euler substep: out = h + DT * tanh(MLP(adj @ h))
__device__ void euler_step(float* sm, int t, const float* __restrict__ adjb,
                           const float* __restrict__ hb, int bcast, int v0,
                           const float* __restrict__ bin,
                           const float* __restrict__ bh0,
                           const float* __restrict__ bh1,
                           const float* __restrict__ bout,
                           float* __restrict__ out1, float* __restrict__ out2) {
    // prefetch residual h values for the final layer (consumed much later)
    const int fc2 = (t & 31) * 2;
    const int fr2 = (t >> 5) * 2;
    float2 hpA, hpB;
    if (bcast) {
        hpA = *(const float2*)(hb + fc2);
        hpB = hpA;
    } else {
        hpA = *(const float2*)(hb + (v0 + fr2) * ND + fc2);
        hpB = *(const float2*)(hb + (v0 + fr2 + 1) * ND + fc2);
    }

    stage_agg(sm, t, adjb, hb, bcast);
    float* xA = sm + WORK0;
    float* xB = sm + WORK1;
    layer128<ND>(t, sm + W_IN, bin, xA, xB);
    __syncthreads();
    layer128<NH>(t, sm + W_H0, bh0, xB, xA);
    __syncthreads();
    layer128<NH>(t, sm + W_H1, bh1, xA, xB);
    __syncthreads();
    // final layer 128 -> 64, tile = 2 rows x 2 cols
    {
        float b0 = __ldg(bout + fc2), b1 = __ldg(bout + fc2 + 1);
        float a00 = 0.f, a01 = 0.f, a10 = 0.f, a11 = 0.f;
        const float* xp = xB + fr2;
        const float* wp = sm + W_OUT + fc2;
#pragma unroll 4
        for (int k = 0; k < NH; k++) {
            float2 xv = *(const float2*)xp;
            float2 wv = *(const float2*)wp;
            xp += XS;
            wp += ND;
            a00 += xv.x * wv.x; a01 += xv.x * wv.y;
            a10 += xv.y * wv.x; a11 += xv.y * wv.y;
        }
#pragma unroll
        for (int rr = 0; rr < 2; rr++) {
            int r = fr2 + rr;
            float2 hp = (rr == 0) ? hpA : hpB;
            float d0 = (rr == 0) ? a00 : a10;
            float d1 = (rr == 0) ? a01 : a11;
            float2 o;
            o.x = hp.x + 0.25f * fast_tanh(d0 + b0);
            o.y = hp.y + 0.25f * fast_tanh(d1 + b1);
            *(float2*)(out1 + (v0 + r) * ND + fc2) = o;
            if (out2) *(float2*)(out2 + (v0 + r) * ND + fc2) = o;
        }
    }
}

// GRU correction; weights from smem overlay. Also writes x_pred row (xp != null).
__device__ void gru_step(float* sm, int t, const float* __restrict__ adjb,
                         const float* __restrict__ hb, int v0,
                         const float* __restrict__ vrow, const float* __restrict__ mrowg,
                         const float* __restrict__ br, const float* __restrict__ bz,
                         const float* __restrict__ bg, const float* __restrict__ bo,
                         float* __restrict__ post, float* __restrict__ xp) {
    float* aggT = sm + WORK0;            // 64*XS
    float* h1T = sm + WORK0 + 64 * XS;   // 64*XS
    float* xT = sm + WORK0 + 128 * XS;   // 32*XS
    float* mrow = sm + WORK0 + 160 * XS; // 16
    float* rT = sm + WORK1;
    float* zT = sm + WORK1 + 64 * XS;

    // prefetch own-row h1 scalars and x/mask pairs (consumed after stage_agg)
    float h1pf[4];
#pragma unroll
    for (int i = 0; i < 4; i++) {
        int idx = t + i * NTHR;
        int r = idx >> 6, d = idx & 63;
        h1pf[i] = hb[(v0 + r) * ND + d];
    }
    float vpf[2], mpf[2];
#pragma unroll
    for (int i = 0; i < 2; i++) {
        int idx = t + i * NTHR;  // 0..511
        int r = idx >> 5, c = idx & 31;
        vpf[i] = vrow[(v0 + r) * NI + c];
        mpf[i] = mrowg[(v0 + r) * NI + c];
    }

    stage_agg(sm, t, adjb, hb, 0);  // -> aggT (WORK0 [d][r])

    // stage h1T, xT, mrow (WORK0 tail; after stage_agg's final sync)
#pragma unroll
    for (int i = 0; i < 4; i++) {
        int idx = t + i * NTHR;
        int r = idx >> 6, d = idx & 63;
        h1T[d * XS + r] = h1pf[i];
    }
#pragma unroll
    for (int i = 0; i < 2; i++) {
        int idx = t + i * NTHR;
        int r = idx >> 5, c = idx & 31;
        xT[c * XS + r] = vpf[i] * mpf[i];
    }
    if (t < ROWS) {
        float s = 0.f;
        for (int c = 0; c < NI; c++) s += fabsf(mrowg[(v0 + t) * NI + c]);
        mrow[t] = (s > 1e-4f) ? 1.0f : 0.0f;
    }
    __syncthreads();

    const int c2 = (t & 31) * 2;
    const int r2 = (t >> 5) * 2;
    // r and z gates (Kin = 96 = [x(32), agg(64)])
    {
        float br0 = __ldg(br + c2), br1 = __ldg(br + c2 + 1);
        float bz0 = __ldg(bz + c2), bz1 = __ldg(bz + c2 + 1);
        float ar00 = 0.f, ar01 = 0.f, ar10 = 0.f, ar11 = 0.f;
        float az00 = 0.f, az01 = 0.f, az10 = 0.f, az11 = 0.f;
        const float* wr = sm + G_WR + c2;
        const float* wz = sm + G_WZ + c2;
        const float* xq = xT + r2;
#pragma unroll 4
        for (int k = 0; k < NI; k++) {
            float2 xv = *(const float2*)xq;
            float2 wrv = *(const float2*)wr;
            float2 wzv = *(const float2*)wz;
            xq += XS; wr += ND; wz += ND;
            ar00 += xv.x * wrv.x; ar01 += xv.x * wrv.y;
            ar10 += xv.y * wrv.x; ar11 += xv.y * wrv.y;
            az00 += xv.x * wzv.x; az01 += xv.x * wzv.y;
            az10 += xv.y * wzv.x; az11 += xv.y * wzv.y;
        }
        const float* xa = aggT + r2;
#pragma unroll 4
        for (int k = 0; k < ND; k++) {
            float2 xv = *(const float2*)xa;
            float2 wrv = *(const float2*)wr;
            float2 wzv = *(const float2*)wz;
            xa += XS; wr += ND; wz += ND;
            ar00 += xv.x * wrv.x; ar01 += xv.x * wrv.y;
            ar10 += xv.y * wrv.x; ar11 += xv.y * wrv.y;
            az00 += xv.x * wzv.x; az01 += xv.x * wzv.y;
            az10 += xv.y * wzv.x; az11 += xv.y * wzv.y;
        }
        rT[c2 * XS + r2 + 0] = fast_sig(ar00 + br0);
        rT[c2 * XS + r2 + 1] = fast_sig(ar10 + br0);
        rT[(c2 + 1) * XS + r2 + 0] = fast_sig(ar01 + br1);
        rT[(c2 + 1) * XS + r2 + 1] = fast_sig(ar11 + br1);
        zT[c2 * XS + r2 + 0] = fast_sig(az00 + bz0);
        zT[c2 * XS + r2 + 1] = fast_sig(az10 + bz0);
        zT[(c2 + 1) * XS + r2 + 0] = fast_sig(az01 + bz1);
        zT[(c2 + 1) * XS + r2 + 1] = fast_sig(az11 + bz1);
    }
    __syncthreads();
    // rT <- r * agg (elementwise)
#pragma unroll
    for (int i = 0; i < 4; i++) {
        int idx = t + i * NTHR;
        int r = idx >> 6, d = idx & 63;
        rT[d * XS + r] *= aggT[d * XS + r];
    }
    __syncthreads();
    // g gate + combine + store post
    {
        float bg0 = __ldg(bg + c2), bg1 = __ldg(bg + c2 + 1);
        float ag00 = 0.f, ag01 = 0.f, ag10 = 0.f, ag11 = 0.f;
        const float* wg = sm + G_WG + c2;
        const float* xq = xT + r2;
#pragma unroll 4
        for (int k = 0; k < NI; k++) {
            float2 xv = *(const float2*)xq;
            float2 wgv = *(const float2*)wg;
            xq += XS; wg += ND;
            ag00 += xv.x * wgv.x; ag01 += xv.x * wgv.y;
            ag10 += xv.y * wgv.x; ag11 += xv.y * wgv.y;
        }
        const float* xr = rT + r2;
#pragma unroll 4
        for (int k = 0; k < ND; k++) {
            float2 xv = *(const float2*)xr;
            float2 wgv = *(const float2*)wg;
            xr += XS; wg += ND;
            ag00 += xv.x * wgv.x; ag01 += xv.x * wgv.y;
            ag10 += xv.y * wgv.x; ag11 += xv.y * wgv.y;
        }
#pragma unroll
        for (int rr = 0; rr < 2; rr++) {
            int r = r2 + rr;
            float m = mrow[r];
            float g0 = fast_tanh(((rr == 0) ? ag00 : ag10) + bg0);
            float g1 = fast_tanh(((rr == 0) ? ag01 : ag11) + bg1);
            float z0 = zT[c2 * XS + r], z1 = zT[(c2 + 1) * XS + r];
            float h0v = h1T[c2 * XS + r], h1v = h1T[(c2 + 1) * XS + r];
            float n0 = (1.f - z0) * h0v + z0 * g0;
            float n1 = (1.f - z1) * h1v + z1 * g1;
            float2 o;
            o.x = h0v + m * (n0 - h0v);
            o.y = h1v + m * (n1 - h1v);
            *(float2*)(post + (v0 + r) * ND + c2) = o;
        }
    }
    // x_pred row from h1 (pre state)
    if (xp) {
        const int cx = (t & 15) * 2;
        const int r = t >> 4;
        float a0 = 0.f, a1 = 0.f;
        const float* wo = sm + G_WO + cx;
        const float* hq = h1T + r;
#pragma unroll 4
        for (int k = 0; k < ND; k++) {
            float hv = *hq;
            float2 w = *(const float2*)wo;
            hq += XS; wo += NI;
            a0 += hv * w.x; a1 += hv * w.y;
        }
        float2 o;
        o.x = a0 + __ldg(bo + cx);
        o.y = a1 + __ldg(bo + cx + 1);
        *(float2*)(xp + (v0 + r) * NI + cx) = o;
    }
}

__global__ void init_kernel(float* __restrict__ trj) {
    int i = threadIdx.x;
    if (i < 197) trj[i] = 0.25f * (float)i;
}

__global__ void __launch_bounds__(NTHR, 1) __cluster_dims__(CLUSTER, 1, 1)
node_persist(
    const float* __restrict__ values, const float* __restrict__ masks,
    const float* __restrict__ adj, const float* __restrict__ h0,
    const float* __restrict__ Wo_g, const float* __restrict__ bo,
    const float* __restrict__ Win_g, const float* __restrict__ bin,
    const float* __restrict__ Wh_g, const float* __restrict__ bh,
    const float* __restrict__ Wode_g, const float* __restrict__ bode,
    const float* __restrict__ Wr_g, const float* __restrict__ br,
    const float* __restrict__ Wz_g, const float* __restrict__ bz,
    const float* __restrict__ Wg_g, const float* __restrict__ bg,
    float* __restrict__ XP, float* __restrict__ PRE,
    float* __restrict__ PREN, float* __restrict__ POST) {
    extern __shared__ __align__(16) float sm[];
    const int t = threadIdx.x;
    const int b = blockIdx.x >> 4;
    const int v0 = (blockIdx.x & 15) * ROWS;
    const float* adjb = adj + ((long long)b * NV + v0) * NV;
    const long long SL = (long long)NV * ND;
    float* PREb = PRE + (long long)b * 197 * SL;
    float* PRENb = PREN + (long long)b * NT * SL;
    float* POSTb = POST + (long long)b * NT * SL;
    float* XPb = XP + (long long)b * 49 * NV * NI;
    const float* valb = values + (long long)b * NT * NV * NI;
    const float* mskb = masks + (long long)b * NT * NV * NI;

    // weights resident in smem for the whole kernel
    smcopy(sm + W_IN, Win_g, 8192, t);
    smcopy(sm + W_H0, Wh_g, 16384, t);
    smcopy(sm + W_H1, Wh_g + 16384, 16384, t);
    smcopy(sm + W_OUT, Wode_g, 8192, t);
    __syncthreads();

    // t=0: single Euler from broadcast h0
    euler_step(sm, t, adjb, h0, 1, v0, bin, bh, bh + NH, bode, PREb, PRENb);
    cluster_barrier();

    for (int tt = 0; tt < NT; tt++) {
        // overlay GRU weights into W_H0/W_H1 space
        smcopy(sm + G_WR, Wr_g, 6144, t);
        smcopy(sm + G_WZ, Wz_g, 6144, t);
        smcopy(sm + G_WG, Wg_g, 6144, t);
        smcopy(sm + G_WO, Wo_g, 2048, t);
        __syncthreads();
        gru_step(sm, t, adjb, PRENb + (long long)tt * SL, v0,
                 valb + (long long)tt * NV * NI, mskb + (long long)tt * NV * NI,
                 br, bz, bg, bo, POSTb + (long long)tt * SL,
                 tt ? (XPb + (long long)(tt - 1) * NV * NI) : nullptr);
        cluster_barrier();
        if (tt < NT - 1) {
            // restore Wh0/Wh1
            smcopy(sm + W_H0, Wh_g, 16384, t);
            smcopy(sm + W_H1, Wh_g + 16384, 16384, t);
            __syncthreads();
            const float* hin = POSTb + (long long)tt * SL;
#pragma unroll 1
            for (int k = 0; k < 4; k++) {
                float* o1 = PREb + (long long)(1 + 4 * tt + k) * SL;
                float* o2 = (k == 3) ? (PRENb + (long long)(tt + 1) * SL) : nullptr;
                euler_step(sm, t, adjb, hin, 0, v0, bin, bh, bh + NH, bode, o1, o2);
                cluster_barrier();
                hin = o1;
            }
        }
    }
}

extern "C" void kernel_launch(void* const* d_in, const int* in_sizes, int n_in,
                              void* d_out, int out_size) {
    const float* values = (const float*)d_in[0];
    const float* masks  = (const float*)d_in[1];
    const float* adj    = (const float*)d_in[2];
    const float* h0     = (const float*)d_in[3];
    const float* W_out  = (const float*)d_in[4];
    const float* b_out  = (const float*)d_in[5];
    const float* Win    = (const float*)d_in[6];
    const float* bin    = (const float*)d_in[7];
    const float* Wh     = (const float*)d_in[8];
    const float* bh     = (const float*)d_in[9];
    const float* Wode   = (const float*)d_in[10];
    const float* bode   = (const float*)d_in[11];
    const float* Wr     = (const float*)d_in[12];
    const float* br     = (const float*)d_in[13];
    const float* Wz     = (const float*)d_in[14];
    const float* bz     = (const float*)d_in[15];
    const float* Wg     = (const float*)d_in[16];
    const float* bg     = (const float*)d_in[17];

    float* out = (float*)d_out;
    float* XP   = out;                                        // (8,49,256,32)
    float* PRE  = XP + (long long)NB * 49 * NV * NI;          // (8,197,256,64)
    float* PREN = PRE + (long long)NB * 197 * NV * ND;        // (8,50,256,64)
    float* POST = PREN + (long long)NB * NT * NV * ND;        // (8,50,256,64)
    float* TRJ  = POST + (long long)NB * NT * NV * ND;        // (197,)

    const size_t smbytes = SM_FLOATS * sizeof(float);         // 229376
    static int configured = 0;
    if (!configured) {
        cudaFuncSetAttribute(node_persist,
                             cudaFuncAttributeNonPortableClusterSizeAllowed, 1);
        cudaFuncSetAttribute(node_persist,
                             cudaFuncAttributeMaxDynamicSharedMemorySize, (int)smbytes);
        configured = 1;
    }

    init_kernel<<<1, 256>>>(TRJ);
    node_persist<<<GRID, NTHR, smbytes>>>(values, masks, adj, h0, W_out, b_out,
                                          Win, bin, Wh, bh, Wode, bode,
                                          Wr, br, Wz, bz, Wg, bg,
                                          XP, PRE, PREN, POST);
}

// round 12
// speedup vs baseline: 1.2003x; 1.0001x over previous
#include <cuda_runtime.h>

#define NB 8
#define NV 256
#define ND 64
#define NH 128
#define NI 32
#define NT 50
#define ROWS 16
#define XS 20                 // smem activation stride
#define NTHR 256
#define GRID 128              // 16 blocks per batch element = 1 cluster
#define CLUSTER 16

// ---- shared memory layout (floats) ----
#define WORK0 0               // 4096  (adj tile / xA / gru region0)
#define WORK1 4096            // 4096  (h chunk double-buffer / partials / xB / rT,zT)
#define W_IN  8192            // 8192  (64x128)
#define W_H0  16384           // 16384 (128x128)
#define W_H1  32768           // 16384 (128x128)
#define W_OUT 49152           // 8192  (128x64)
#define SM_FLOATS 57344       // 224 KB
// GRU overlay (reuses W_H0/W_H1 space; reloaded after GRU)
#define G_WR  16384           // 96x64 = 6144
#define G_WZ  (16384 + 6144)
#define G_WG  (16384 + 12288)
#define G_WO  (16384 + 18432) // 64x32 = 2048

__device__ __forceinline__ float fast_tanh(float x) {
    float e = __expf(-2.0f * fabsf(x));
    float t = __fdividef(1.0f - e, 1.0f + e);
    return copysignf(t, x);
}
__device__ __forceinline__ float fast_sig(float x) {
    return __fdividef(1.0f, 1.0f + __expf(-x));
}

__device__ __forceinline__ void cluster_barrier() {
    __syncthreads();
    __threadfence();
    asm volatile("barrier.cluster.arrive.aligned;" ::: "memory");
    asm volatile("barrier.cluster.wait.aligned;" ::: "memory");
}

__device__ __forceinline__ void smcopy(float* dst, const float* src, int nfloats, int t) {
    float4* d4 = (float4*)dst;
    const float4* s4 = (const float4*)src;
    int n4 = nfloats >> 2;
    for (int i = t; i < n4; i += NTHR) d4[i] = s4[i];
}

// hidden layer, Kout=128: 16 rows x 128 cols, 256 threads, tile 4 rows x 2 cols.
// W in shared memory. xin/xout in [k][row] layout, stride XS.
template <int KIN>
__device__ __forceinline__ void layer128(int t, const float* W,
                                         const float* __restrict__ bias,
                                         const float* xin, float* xout) {
    const int c2 = (t & 63) * 2;
    const int r4 = (t >> 6) * 4;
    float b0 = __ldg(bias + c2), b1 = __ldg(bias + c2 + 1);
    float a00 = 0.f, a01 = 0.f, a10 = 0.f, a11 = 0.f;
    float a20 = 0.f, a21 = 0.f, a30 = 0.f, a31 = 0.f;
    const float* xp = xin + r4;
    const float* wp = W + c2;
#pragma unroll 4
    for (int k = 0; k < KIN; k++) {
        float4 xv = *(const float4*)xp;
        float2 wv = *(const float2*)wp;
        xp += XS;
        wp += NH;
        a00 += xv.x * wv.x; a01 += xv.x * wv.y;
        a10 += xv.y * wv.x; a11 += xv.y * wv.y;
        a20 += xv.z * wv.x; a21 += xv.z * wv.y;
        a30 += xv.w * wv.x; a31 += xv.w * wv.y;
    }
    xout[c2 * XS + r4 + 0] = fast_tanh(a00 + b0);
    xout[c2 * XS + r4 + 1] = fast_tanh(a10 + b0);
    xout[c2 * XS + r4 + 2] = fast_tanh(a20 + b0);
    xout[c2 * XS + r4 + 3] = fast_tanh(a30 + b0);
    xout[(c2 + 1) * XS + r4 + 0] = fast_tanh(a01 + b1);
    xout[(c2 + 1) * XS + r4 + 1] = fast_tanh(a11 + b1);
    xout[(c2 + 1) * XS + r4 + 2] = fast_tanh(a21 + b1);
    xout[(c2 + 1) * XS + r4 + 3] = fast_tanh(a31 + b1);
}

// agg = adj @ h -> WORK0 as [d][r] (stride XS).
// h is streamed through smem in 8 chunks of 32 rows (8KB), double-buffered in
// WORK1; after the last chunk, WORK1 is reused for the wq-partial buffer.
// Thread map: d4 = (t&15)*4, rg = ((t>>4)&3)*4, wq = t>>6 (quarter of each chunk).
__device__ __forceinline__ void stage_agg(float* sm, int t, const float* __restrict__ adjb,
                                          const float* __restrict__ hb, int bcast) {
    const int d4 = (t & 15) * 4;
    const int rg = ((t >> 4) & 3) * 4;
    const int wq = t >> 6;  // 0..3
    float4 acc[4];
    acc[0] = acc[1] = acc[2] = acc[3] = make_float4(0.f, 0.f, 0.f, 0.f);

    if (bcast) {
        float4 h4 = *(const float4*)(hb + d4);   // h0 broadcast (64 floats)
        // stage adj tile
#pragma unroll
        for (int i = 0; i < 4; i++) {
            int idx = t + i * NTHR;
            *(float4*)(sm + idx * 4) = *(const float4*)(adjb + idx * 4);
        }
        __syncthreads();
#pragma unroll 4
        for (int w = 0; w < 64; w++) {
            int wa = wq * 64 + w;
#pragma unroll
            for (int rr = 0; rr < 4; rr++) {
                float a = sm[(rg + rr) * NV + wa];
                acc[rr].x += a * h4.x; acc[rr].y += a * h4.y;
                acc[rr].z += a * h4.z; acc[rr].w += a * h4.w;
            }
        }
        __syncthreads();
    } else {
        float* hbuf = sm + WORK1;  // 2 x 2048 floats (32 rows x 64 each)
        // prefetch chunk 0 into registers
        float4 p0 = *(const float4*)(hb + t * 8);
        float4 p1 = *(const float4*)(hb + t * 8 + 4);
        // stage adj tile
#pragma unroll
        for (int i = 0; i < 4; i++) {
            int idx = t + i * NTHR;
            *(float4*)(sm + idx * 4) = *(const float4*)(adjb + idx * 4);
        }
        *(float4*)(hbuf + t * 8) = p0;
        *(float4*)(hbuf + t * 8 + 4) = p1;
#pragma unroll 2
        for (int c = 0; c < 8; c++) {
            float4 q0, q1;
            if (c < 7) {
                const float* src = hb + (c + 1) * 2048 + t * 8;
                q0 = *(const float4*)src;
                q1 = *(const float4*)(src + 4);
            }
            __syncthreads();  // chunk c staged; previous compute done
            const float* hc = hbuf + (c & 1) * 2048;
#pragma unroll
            for (int w = 0; w < 8; w++) {
                int wl = wq * 8 + w;            // row within chunk
                float4 h4 = *(const float4*)(hc + wl * 64 + d4);
                int wa = c * 32 + wl;           // adj column
#pragma unroll
                for (int rr = 0; rr < 4; rr++) {
                    float a = sm[(rg + rr) * NV + wa];
                    acc[rr].x += a * h4.x; acc[rr].y += a * h4.y;
                    acc[rr].z += a * h4.z; acc[rr].w += a * h4.w;
                }
            }
            if (c < 7) {
                float* dst = hbuf + ((c + 1) & 1) * 2048 + t * 8;
                *(float4*)dst = q0;
                *(float4*)(dst + 4) = q1;
            }
        }
        __syncthreads();  // all chunk compute done; hbuf now dead
    }

    // wq-partials into WORK1 (h buffer dead)
    float* pb = sm + WORK1;
#pragma unroll
    for (int rr = 0; rr < 4; rr++)
        *(float4*)(pb + wq * 1024 + (rg + rr) * ND + d4) = acc[rr];
    __syncthreads();
    // reduce 4 partials -> xA [d][r] in WORK0 (adj dead)
#pragma unroll
    for (int i = 0; i < 4; i++) {
        int idx = t + i * NTHR;  // 0..1023
        int r = idx >> 6, d = idx & 63;
        float s = pb[d + r * ND] + pb[1024 + d + r * ND] +
                  pb[2048 + d + r * ND] + pb[3072 + d + r * ND];
        sm[WORK0 + d * XS + r] = s;
    }
    __syncthreads();
}

// one Euler substep: out = h + DT * tanh(MLP(adj @ h))
__device__ void euler_step(float* sm, int t, const float* __restrict__ adjb,
                           const float* __restrict__ hb, int bcast, int v0,
                           const float* __restrict__ bin,
                           const float* __restrict__ bh0,
                           const float* __restrict__ bh1,
                           const float* __restrict__ bout,
                           float* __restrict__ out1, float* __restrict__ out2) {
    // prefetch residual h values for the final layer (consumed much later)
    const int fc2 = (t & 31) * 2;
    const int fr2 = (t >> 5) * 2;
    float2 hpA, hpB;
    if (bcast) {
        hpA = *(const float2*)(hb + fc2);
        hpB = hpA;
    } else {
        hpA = *(const float2*)(hb + (v0 + fr2) * ND + fc2);
        hpB = *(const float2*)(hb + (v0 + fr2 + 1) * ND + fc2);
    }

    stage_agg(sm, t, adjb, hb, bcast);
    float* xA = sm + WORK0;
    float* xB = sm + WORK1;
    layer128<ND>(t, sm + W_IN, bin, xA, xB);
    __syncthreads();
    layer128<NH>(t, sm + W_H0, bh0, xB, xA);
    __syncthreads();
    layer128<NH>(t, sm + W_H1, bh1, xA, xB);
    __syncthreads();
    // final layer 128 -> 64, tile = 2 rows x 2 cols
    {
        float b0 = __ldg(bout + fc2), b1 = __ldg(bout + fc2 + 1);
        float a00 = 0.f, a01 = 0.f, a10 = 0.f, a11 = 0.f;
        const float* xp = xB + fr2;
        const float* wp = sm + W_OUT + fc2;
#pragma unroll 4
        for (int k = 0; k < NH; k++) {
            float2 xv = *(const float2*)xp;
            float2 wv = *(const float2*)wp;
            xp += XS;
            wp += ND;
            a00 += xv.x * wv.x; a01 += xv.x * wv.y;
            a10 += xv.y * wv.x; a11 += xv.y * wv.y;
        }
#pragma unroll
        for (int rr = 0; rr < 2; rr++) {
            int r = fr2 + rr;
            float2 hp = (rr == 0) ? hpA : hpB;
            float d0 = (rr == 0) ? a00 : a10;
            float d1 = (rr == 0) ? a01 : a11;
            float2 o;
            o.x = hp.x + 0.25f * fast_tanh(d0 + b0);
            o.y = hp.y + 0.25f * fast_tanh(d1 + b1);
            *(float2*)(out1 + (v0 + r) * ND + fc2) = o;
            if (out2) *(float2*)(out2 + (v0 + r) * ND + fc2) = o;
        }
    }
}

// GRU correction; weights from smem overlay. Also writes x_pred row (xp != null).
__device__ void gru_step(float* sm, int t, const float* __restrict__ adjb,
                         const float* __restrict__ hb, int v0,
                         const float* __restrict__ vrow, const float* __restrict__ mrowg,
                         const float* __restrict__ br, const float* __restrict__ bz,
                         const float* __restrict__ bg, const float* __restrict__ bo,
                         float* __restrict__ post, float* __restrict__ xp) {
    float* aggT = sm + WORK0;            // 64*XS
    float* h1T = sm + WORK0 + 64 * XS;   // 64*XS
    float* xT = sm + WORK0 + 128 * XS;   // 32*XS
    float* mrow = sm + WORK0 + 160 * XS; // 16
    float* rT = sm + WORK1;
    float* zT = sm + WORK1 + 64 * XS;

    // prefetch own-row h1 scalars and x/mask pairs (consumed after stage_agg)
    float h1pf[4];
#pragma unroll
    for (int i = 0; i < 4; i++) {
        int idx = t + i * NTHR;
        int r = idx >> 6, d = idx & 63;
        h1pf[i] = hb[(v0 + r) * ND + d];
    }
    float vpf[2], mpf[2];
#pragma unroll
    for (int i = 0; i < 2; i++) {
        int idx = t + i * NTHR;  // 0..511
        int r = idx >> 5, c = idx & 31;
        vpf[i] = vrow[(v0 + r) * NI + c];
        mpf[i] = mrowg[(v0 + r) * NI + c];
    }

    stage_agg(sm, t, adjb, hb, 0);  // -> aggT (WORK0 [d][r])

    // stage h1T, xT, mrow (WORK0 tail; after stage_agg's final sync)
#pragma unroll
    for (int i = 0; i < 4; i++) {
        int idx = t + i * NTHR;
        int r = idx >> 6, d = idx & 63;
        h1T[d * XS + r] = h1pf[i];
    }
#pragma unroll
    for (int i = 0; i < 2; i++) {
        int idx = t + i * NTHR;
        int r = idx >> 5, c = idx & 31;
        xT[c * XS + r] = vpf[i] * mpf[i];
    }
    if (t < ROWS) {
        float s = 0.f;
        for (int c = 0; c < NI; c++) s += fabsf(mrowg[(v0 + t) * NI + c]);
        mrow[t] = (s > 1e-4f) ? 1.0f : 0.0f;
    }
    __syncthreads();

    const int c2 = (t & 31) * 2;
    const int r2 = (t >> 5) * 2;
    // r and z gates (Kin = 96 = [x(32), agg(64)])
    {
        float br0 = __ldg(br + c2), br1 = __ldg(br + c2 + 1);
        float bz0 = __ldg(bz + c2), bz1 = __ldg(bz + c2 + 1);
        float ar00 = 0.f, ar01 = 0.f, ar10 = 0.f, ar11 = 0.f;
        float az00 = 0.f, az01 = 0.f, az10 = 0.f, az11 = 0.f;
        const float* wr = sm + G_WR + c2;
        const float* wz = sm + G_WZ + c2;
        const float* xq = xT + r2;
#pragma unroll 4
        for (int k = 0; k < NI; k++) {
            float2 xv = *(const float2*)xq;
            float2 wrv = *(const float2*)wr;
            float2 wzv = *(const float2*)wz;
            xq += XS; wr += ND; wz += ND;
            ar00 += xv.x * wrv.x; ar01 += xv.x * wrv.y;
            ar10 += xv.y * wrv.x; ar11 += xv.y * wrv.y;
            az00 += xv.x * wzv.x; az01 += xv.x * wzv.y;
            az10 += xv.y * wzv.x; az11 += xv.y * wzv.y;
        }
        const float* xa = aggT + r2;
#pragma unroll 4
        for (int k = 0; k < ND; k++) {
            float2 xv = *(const float2*)xa;
            float2 wrv = *(const float2*)wr;
            float2 wzv = *(const float2*)wz;
            xa += XS; wr += ND; wz += ND;
            ar00 += xv.x * wrv.x; ar01 += xv.x * wrv.y;
            ar10 += xv.y * wrv.x; ar11 += xv.y * wrv.y;
            az00 += xv.x * wzv.x; az01 += xv.x * wzv.y;
            az10 += xv.y * wzv.x; az11 += xv.y * wzv.y;
        }
        rT[c2 * XS + r2 + 0] = fast_sig(ar00 + br0);
        rT[c2 * XS + r2 + 1] = fast_sig(ar10 + br0);
        rT[(c2 + 1) * XS + r2 + 0] = fast_sig(ar01 + br1);
        rT[(c2 + 1) * XS + r2 + 1] = fast_sig(ar11 + br1);
        zT[c2 * XS + r2 + 0] = fast_sig(az00 + bz0);
        zT[c2 * XS + r2 + 1] = fast_sig(az10 + bz0);
        zT[(c2 + 1) * XS + r2 + 0] = fast_sig(az01 + bz1);
        zT[(c2 + 1) * XS + r2 + 1] = fast_sig(az11 + bz1);
    }
    __syncthreads();
    // rT <- r * agg (elementwise)
#pragma unroll
    for (int i = 0; i < 4; i++) {
        int idx = t + i * NTHR;
        int r = idx >> 6, d = idx & 63;
        rT[d * XS + r] *= aggT[d * XS + r];
    }
    __syncthreads();
    // g gate + combine + store post
    {
        float bg0 = __ldg(bg + c2), bg1 = __ldg(bg + c2 + 1);
        float ag00 = 0.f, ag01 = 0.f, ag10 = 0.f, ag11 = 0.f;
        const float* wg = sm + G_WG + c2;
        const float* xq = xT + r2;
#pragma unroll 4
        for (int k = 0; k < NI; k++) {
            float2 xv = *(const float2*)xq;
            float2 wgv = *(const float2*)wg;
            xq += XS; wg += ND;
            ag00 += xv.x * wgv.x; ag01 += xv.x * wgv.y;
            ag10 += xv.y * wgv.x; ag11 += xv.y * wgv.y;
        }
        const float* xr = rT + r2;
#pragma unroll 4
        for (int k = 0; k < ND; k++) {
            float2 xv = *(const float2*)xr;
            float2 wgv = *(const float2*)wg;
            xr += XS; wg += ND;
            ag00 += xv.x * wgv.x; ag01 += xv.x * wgv.y;
            ag10 += xv.y * wgv.x; ag11 += xv.y * wgv.y;
        }
#pragma unroll
        for (int rr = 0; rr < 2; rr++) {
            int r = r2 + rr;
            float m = mrow[r];
            float g0 = fast_tanh(((rr == 0) ? ag00 : ag10) + bg0);
            float g1 = fast_tanh(((rr == 0) ? ag01 : ag11) + bg1);
            float z0 = zT[c2 * XS + r], z1 = zT[(c2 + 1) * XS + r];
            float h0v = h1T[c2 * XS + r], h1v = h1T[(c2 + 1) * XS + r];
            float n0 = (1.f - z0) * h0v + z0 * g0;
            float n1 = (1.f - z1) * h1v + z1 * g1;
            float2 o;
            o.x = h0v + m * (n0 - h0v);
            o.y = h1v + m * (n1 - h1v);
            *(float2*)(post + (v0 + r) * ND + c2) = o;
        }
    }
    // x_pred row from h1 (pre state)
    if (xp) {
        const int cx = (t & 15) * 2;
        const int r = t >> 4;
        float a0 = 0.f, a1 = 0.f;
        const float* wo = sm + G_WO + cx;
        const float* hq = h1T + r;
#pragma unroll 4
        for (int k = 0; k < ND; k++) {
            float hv = *hq;
            float2 w = *(const float2*)wo;
            hq += XS; wo += NI;
            a0 += hv * w.x; a1 += hv * w.y;
        }
        float2 o;
        o.x = a0 + __ldg(bo + cx);
        o.y = a1 + __ldg(bo + cx + 1);
        *(float2*)(xp + (v0 + r) * NI + cx) = o;
    }
}

__global__ void init_kernel(float* __restrict__ trj) {
    int i = threadIdx.x;
    if (i < 197) trj[i] = 0.25f * (float)i;
}

__global__ void __launch_bounds__(NTHR, 1) __cluster_dims__(CLUSTER, 1, 1)
node_persist(
    const float* __restrict__ values, const float* __restrict__ masks,
    const float* __restrict__ adj, const float* __restrict__ h0,
    const float* __restrict__ Wo_g, const float* __restrict__ bo,
    const float* __restrict__ Win_g, const float* __restrict__ bin,
    const float* __restrict__ Wh_g, const float* __restrict__ bh,
    const float* __restrict__ Wode_g, const float* __restrict__ bode,
    const float* __restrict__ Wr_g, const float* __restrict__ br,
    const float* __restrict__ Wz_g, const float* __restrict__ bz,
    const float* __restrict__ Wg_g, const float* __restrict__ bg,
    float* __restrict__ XP, float* __restrict__ PRE,
    float* __restrict__ PREN, float* __restrict__ POST) {
    extern __shared__ __align__(16) float sm[];
    const int t = threadIdx.x;
    const int b = blockIdx.x >> 4;
    const int v0 = (blockIdx.x & 15) * ROWS;
    const float* adjb = adj + ((long long)b * NV + v0) * NV;
    const long long SL = (long long)NV * ND;
    float* PREb = PRE + (long long)b * 197 * SL;
    float* PRENb = PREN + (long long)b * NT * SL;
    float* POSTb = POST + (long long)b * NT * SL;
    float* XPb = XP + (long long)b * 49 * NV * NI;
    const float* valb = values + (long long)b * NT * NV * NI;
    const float* mskb = masks + (long long)b * NT * NV * NI;

    // weights resident in smem for the whole kernel
    smcopy(sm + W_IN, Win_g, 8192, t);
    smcopy(sm + W_H0, Wh_g, 16384, t);
    smcopy(sm + W_H1, Wh_g + 16384, 16384, t);
    smcopy(sm + W_OUT, Wode_g, 8192, t);
    __syncthreads();

    // t=0: single Euler from broadcast h0
    euler_step(sm, t, adjb, h0, 1, v0, bin, bh, bh + NH, bode, PREb, PRENb);
    cluster_barrier();

    for (int tt = 0; tt < NT; tt++) {
        // overlay GRU weights into W_H0/W_H1 space
        smcopy(sm + G_WR, Wr_g, 6144, t);
        smcopy(sm + G_WZ, Wz_g, 6144, t);
        smcopy(sm + G_WG, Wg_g, 6144, t);
        smcopy(sm + G_WO, Wo_g, 2048, t);
        __syncthreads();
        gru_step(sm, t, adjb, PRENb + (long long)tt * SL, v0,
                 valb + (long long)tt * NV * NI, mskb + (long long)tt * NV * NI,
                 br, bz, bg, bo, POSTb + (long long)tt * SL,
                 tt ? (XPb + (long long)(tt - 1) * NV * NI) : nullptr);
        cluster_barrier();
        if (tt < NT - 1) {
            // restore Wh0/Wh1
            smcopy(sm + W_H0, Wh_g, 16384, t);
            smcopy(sm + W_H1, Wh_g + 16384, 16384, t);
            __syncthreads();
            const float* hin = POSTb + (long long)tt * SL;
#pragma unroll 1
            for (int k = 0; k < 4; k++) {
                float* o1 = PREb + (long long)(1 + 4 * tt + k) * SL;
                float* o2 = (k == 3) ? (PRENb + (long long)(tt + 1) * SL) : nullptr;
                euler_step(sm, t, adjb, hin, 0, v0, bin, bh, bh + NH, bode, o1, o2);
                cluster_barrier();
                hin = o1;
            }
        }
    }
}

extern "C" void kernel_launch(void* const* d_in, const int* in_sizes, int n_in,
                              void* d_out, int out_size) {
    const float* values = (const float*)d_in[0];
    const float* masks  = (const float*)d_in[1];
    const float* adj    = (const float*)d_in[2];
    const float* h0     = (const float*)d_in[3];
    const float* W_out  = (const float*)d_in[4];
    const float* b_out  = (const float*)d_in[5];
    const float* Win    = (const float*)d_in[6];
    const float* bin    = (const float*)d_in[7];
    const float* Wh     = (const float*)d_in[8];
    const float* bh     = (const float*)d_in[9];
    const float* Wode   = (const float*)d_in[10];
    const float* bode   = (const float*)d_in[11];
    const float* Wr     = (const float*)d_in[12];
    const float* br     = (const float*)d_in[13];
    const float* Wz     = (const float*)d_in[14];
    const float* bz     = (const float*)d_in[15];
    const float* Wg     = (const float*)d_in[16];
    const float* bg     = (const float*)d_in[17];

    float* out = (float*)d_out;
    float* XP   = out;                                        // (8,49,256,32)
    float* PRE  = XP + (long long)NB * 49 * NV * NI;          // (8,197,256,64)
    float* PREN = PRE + (long long)NB * 197 * NV * ND;        // (8,50,256,64)
    float* POST = PREN + (long long)NB * NT * NV * ND;        // (8,50,256,64)
    float* TRJ  = POST + (long long)NB * NT * NV * ND;        // (197,)

    const size_t smbytes = SM_FLOATS * sizeof(float);         // 229376
    static int configured = 0;
    if (!configured) {
        cudaFuncSetAttribute(node_persist,
                             cudaFuncAttributeNonPortableClusterSizeAllowed, 1);
        cudaFuncSetAttribute(node_persist,
                             cudaFuncAttributeMaxDynamicSharedMemorySize, (int)smbytes);
        configured = 1;
    }

    init_kernel<<<1, 256>>>(TRJ);
    node_persist<<<GRID, NTHR, smbytes>>>(values, masks, adj, h0, W_out, b_out,
                                          Win, bin, Wh, bh, Wode, bode,
                                          Wr, br, Wz, bz, Wg, bg,
                                          XP, PRE, PREN, POST);
}